// round 14
// baseline (speedup 1.0000x reference)
#include <cuda_runtime.h>
#include <cuda_fp16.h>
#include <cstdint>

#define B_ 16
#define S_ 2048
#define D_ 128
#define SCALE_ 0.08838834764831845f  // 1/sqrt(128)

#define QLD_ 136   // halves per Q/K smem row (128 data + 8 pad)
#define CLD_ 132   // floats per staging row (128 data + 4 pad)
#define PLD_ 80    // halves per P smem row (64 data + 16 pad)
#define VLD_ 136   // words per Vs2 pair-row (128 data + 8 pad)

__device__ __forceinline__ uint32_t h2u(half2 h) {
    union { half2 h; uint32_t u; } cvt;
    cvt.h = h;
    return cvt.u;
}

__device__ __forceinline__ uint32_t smem_u32(const void* p) {
    uint32_t a;
    asm("{ .reg .u64 t; cvta.to.shared.u64 t, %1; cvt.u32.u64 %0, t; }" : "=r"(a) : "l"(p));
    return a;
}

// D += A*B, m16n8k16 f16 (f32 accum)
__device__ __forceinline__ void mma16(float* d, uint32_t a0, uint32_t a1, uint32_t a2,
                                      uint32_t a3, uint32_t b0, uint32_t b1) {
    asm volatile(
        "mma.sync.aligned.m16n8k16.row.col.f32.f16.f16.f32 "
        "{%0,%1,%2,%3}, {%4,%5,%6,%7}, {%8,%9}, {%0,%1,%2,%3};"
        : "+f"(d[0]), "+f"(d[1]), "+f"(d[2]), "+f"(d[3])
        : "r"(a0), "r"(a1), "r"(a2), "r"(a3), "r"(b0), "r"(b1));
}

#define LDSM4(r0, r1, r2, r3, a) \
    asm volatile("ldmatrix.sync.aligned.m8n8.x4.shared.b16 {%0,%1,%2,%3}, [%4];" \
                 : "=r"(r0), "=r"(r1), "=r"(r2), "=r"(r3) : "r"(a))

// Convert float4 -> 4 halves, one STS.64
__device__ __forceinline__ void store_h4(half* rowp, int c4, float4 v) {
    uint2 u = { h2u(__floats2half2_rn(v.x, v.y)), h2u(__floats2half2_rn(v.z, v.w)) };
    *(uint2*)(rowp + c4) = u;
}

// Permuted half store: within each 16-k group, k=2c+h+8e -> pos 4c+2e+h.
__device__ __forceinline__ void store_perm(half* rowp, int c4, float4 v) {
    const int kk0 = c4 & 15;
    const int pos = ((c4 >> 4) << 4) + ((kk0 & 7) << 1) + ((kk0 >> 3) << 1);
    *(half2*)(rowp + pos)     = __floats2half2_rn(v.x, v.y);
    *(half2*)(rowp + pos + 4) = __floats2half2_rn(v.z, v.w);
}

// =====================================================================
// Kernel 1: scores (round-13 exact: full-depth, 1 mainloop barrier,
// smem-staged coalesced epilogue)
// =====================================================================
#define S_SMEM (2 * 128 * QLD_ * 2)   // 69632 B

__global__ __launch_bounds__(256, 2) void scores_mma(
    const float* __restrict__ q, const float* __restrict__ k,
    const float* __restrict__ mask, float* __restrict__ attn)
{
    extern __shared__ half sm[];
    half* Qh = sm;
    half* Kh = sm + 128 * QLD_;
    float* Cs = (float*)sm;

    const int b  = blockIdx.x;
    const int kt = blockIdx.y * 128;
    const int qt = blockIdx.z * 128;

    const float* qb = q + ((size_t)b * S_ + qt) * D_;
    const float* kb = k + ((size_t)b * S_ + kt) * D_;

    const int tid  = threadIdx.x;
    const int wid  = tid >> 5, lane = tid & 31;
    const int g    = lane >> 2, c = lane & 3;
    const int wm   = (wid & 1) * 64;
    const int wn   = (wid >> 1) * 32;

    const uint32_t qbase = smem_u32(Qh);
    const uint32_t kbase = smem_u32(Kh);
    const int l15 = lane & 15;
    const int khi = (lane >> 4) << 3;

    float acc[4][4][4];
#pragma unroll
    for (int mi = 0; mi < 4; mi++)
#pragma unroll
        for (int ni = 0; ni < 4; ni++)
#pragma unroll
            for (int r = 0; r < 4; r++) acc[mi][ni][r] = 0.0f;

#pragma unroll
    for (int t = 0; t < 16; t++) {
        const int idx = tid + t * 256;
        const int row = idx >> 5, c4 = (idx & 31) * 4;
        const float4 vq = *(const float4*)&qb[(size_t)row * D_ + c4];
        store_h4(&Qh[row * QLD_], c4, vq);
    }
#pragma unroll
    for (int t = 0; t < 16; t++) {
        const int idx = tid + t * 256;
        const int row = idx >> 5, c4 = (idx & 31) * 4;
        const float4 vk = *(const float4*)&kb[(size_t)row * D_ + c4];
        store_h4(&Kh[row * QLD_], c4, vk);
    }
    __syncthreads();

#pragma unroll
    for (int kq = 0; kq < 8; kq++) {
        const int koff = kq * 16 + khi;
        uint32_t b0[4], b1[4];
#pragma unroll
        for (int bg = 0; bg < 2; bg++) {
            const uint32_t a = kbase +
                (uint32_t)(((wn + bg * 16 + l15) * QLD_ + koff) << 1);
            LDSM4(b0[2 * bg], b0[2 * bg + 1], b1[2 * bg], b1[2 * bg + 1], a);
        }
#pragma unroll
        for (int mi = 0; mi < 4; mi++) {
            uint32_t a0, a1, a2, a3;
            const uint32_t a = qbase +
                (uint32_t)(((wm + mi * 16 + l15) * QLD_ + koff) << 1);
            LDSM4(a0, a1, a2, a3, a);
#pragma unroll
            for (int ni = 0; ni < 4; ni++)
                mma16(acc[mi][ni], a0, a1, a2, a3, b0[ni], b1[ni]);
        }
    }

    __syncthreads();
#pragma unroll
    for (int mi = 0; mi < 4; mi++) {
#pragma unroll
        for (int rr = 0; rr < 2; rr++) {
            const int row = wm + mi * 16 + g + rr * 8;
#pragma unroll
            for (int ni = 0; ni < 4; ni++) {
                const int col = wn + ni * 8 + c * 2;
                *(float2*)&Cs[row * CLD_ + col] =
                    make_float2(acc[mi][ni][rr * 2 + 0], acc[mi][ni][rr * 2 + 1]);
            }
        }
    }
    __syncthreads();

    const int lane4 = lane * 4;
#pragma unroll
    for (int j = 0; j < 16; j++) {
        const int row = wid * 16 + j;
        const float4 cv = *(const float4*)&Cs[row * CLD_ + lane4];
        const float4 m4 = *(const float4*)&mask[(size_t)(qt + row) * S_ + kt + lane4];
        float4 o;
        o.x = cv.x * SCALE_ + m4.x;
        o.y = cv.y * SCALE_ + m4.y;
        o.z = cv.z * SCALE_ + m4.z;
        o.w = cv.w * SCALE_ + m4.w;
        *(float4*)&attn[((size_t)b * S_ + qt + row) * S_ + kt + lane4] = o;
    }
}

// =====================================================================
// Kernel 2: in-place row softmax (unchanged).
// =====================================================================
__global__ __launch_bounds__(256) void softmax_kernel(float* __restrict__ attn)
{
    __shared__ float red[256];
    const size_t row = blockIdx.x;
    float* p = attn + row * (size_t)S_;
    const int tid = threadIdx.x;

    float4 v0 = ((const float4*)p)[tid];
    float4 v1 = ((const float4*)p)[tid + 256];

    float m = fmaxf(fmaxf(fmaxf(v0.x, v0.y), fmaxf(v0.z, v0.w)),
                    fmaxf(fmaxf(v1.x, v1.y), fmaxf(v1.z, v1.w)));
    red[tid] = m;
    __syncthreads();
#pragma unroll
    for (int s = 128; s > 0; s >>= 1) {
        if (tid < s) red[tid] = fmaxf(red[tid], red[tid + s]);
        __syncthreads();
    }
    m = red[0];
    __syncthreads();

    v0.x = __expf(v0.x - m); v0.y = __expf(v0.y - m);
    v0.z = __expf(v0.z - m); v0.w = __expf(v0.w - m);
    v1.x = __expf(v1.x - m); v1.y = __expf(v1.y - m);
    v1.z = __expf(v1.z - m); v1.w = __expf(v1.w - m);

    float sum = (v0.x + v0.y) + (v0.z + v0.w) + (v1.x + v1.y) + (v1.z + v1.w);
    red[tid] = sum;
    __syncthreads();
#pragma unroll
    for (int s = 128; s > 0; s >>= 1) {
        if (tid < s) red[tid] += red[tid + s];
        __syncthreads();
    }
    const float inv = 1.0f / red[0];

    v0.x *= inv; v0.y *= inv; v0.z *= inv; v0.w *= inv;
    v1.x *= inv; v1.y *= inv; v1.z *= inv; v1.w *= inv;
    ((float4*)p)[tid]       = v0;
    ((float4*)p)[tid + 256] = v1;
}

// =====================================================================
// Kernel 3: out[b,q,d] = sum_s P[b,q,s] * V[b,s,d]
// NEW: BK=64 chunks -> 32 iterations, half the barriers, 2x longer
// mma runs, 2x fill MLP. Same permuted-P / half2-paired-V layout.
// =====================================================================
__global__ __launch_bounds__(256, 2) void out_mma(
    const float* __restrict__ attn, const float* __restrict__ v,
    float* __restrict__ out)
{
    __shared__ half Ph[128 * PLD_];        // 20 KB
    __shared__ uint32_t Vs2[32 * VLD_];    // 17.4 KB

    const int b  = blockIdx.x;
    const int qt = blockIdx.y * 128;

    const float* pb = attn + ((size_t)b * S_ + qt) * S_;
    const float* vb = v + (size_t)b * S_ * D_;

    const int tid  = threadIdx.x;
    const int wid  = tid >> 5, lane = tid & 31;
    const int g    = lane >> 2, c = lane & 3;
    const int wm   = (wid & 1) * 64;
    const int wn   = (wid >> 1) * 32;

    const int pr    = tid >> 3;         // pair row 0..31 (k pair 2pr,2pr+1)
    const int dbase = (tid & 7) * 4;    // d stride 32 over 4 sub-blocks

    float acc[4][4][4];
#pragma unroll
    for (int mi = 0; mi < 4; mi++)
#pragma unroll
        for (int ni = 0; ni < 4; ni++)
#pragma unroll
            for (int r = 0; r < 4; r++) acc[mi][ni][r] = 0.0f;

#pragma unroll 1
    for (int k0 = 0; k0 < S_; k0 += 64) {
        // P fill: 128 rows x 64 k (permuted halves), 8 float4/thread
#pragma unroll
        for (int t = 0; t < 8; t++) {
            const int idx = tid + t * 256;
            const int row = idx >> 4, c4 = (idx & 15) * 4;
            const float4 vp = *(const float4*)&pb[(size_t)row * S_ + k0 + c4];
            store_perm(&Ph[row * PLD_], c4, vp);
        }
        // V fill: 64 k-rows -> 32 half2 pair-rows x 128 d
        {
            const float* v0r = vb + (size_t)(k0 + 2 * pr) * D_;
            const float* v1r = v0r + D_;
#pragma unroll
            for (int h = 0; h < 4; h++) {
                const int d = dbase + h * 32;
                const float4 a = *(const float4*)&v0r[d];
                const float4 bb = *(const float4*)&v1r[d];
                uint4 u;
                u.x = h2u(__floats2half2_rn(a.x, bb.x));
                u.y = h2u(__floats2half2_rn(a.y, bb.y));
                u.z = h2u(__floats2half2_rn(a.z, bb.z));
                u.w = h2u(__floats2half2_rn(a.w, bb.w));
                *(uint4*)&Vs2[pr * VLD_ + d] = u;
            }
        }
        __syncthreads();

#pragma unroll
        for (int kq = 0; kq < 4; kq++) {
            const int co = kq * 16 + 4 * c;
            uint32_t bf[4][2];
#pragma unroll
            for (int ni = 0; ni < 4; ni++) {
                const int col = wn + ni * 8 + g;
                bf[ni][0] = Vs2[(kq * 8 + c)     * VLD_ + col];
                bf[ni][1] = Vs2[(kq * 8 + c + 4) * VLD_ + col];
            }
#pragma unroll
            for (int mi = 0; mi < 4; mi++) {
                const int row = wm + mi * 16 + g;
                const uint2 alo = *(const uint2*)&Ph[row * PLD_ + co];
                const uint2 ahi = *(const uint2*)&Ph[(row + 8) * PLD_ + co];
#pragma unroll
                for (int ni = 0; ni < 4; ni++)
                    mma16(acc[mi][ni], alo.x, ahi.x, alo.y, ahi.y, bf[ni][0], bf[ni][1]);
            }
        }
        __syncthreads();
    }

#pragma unroll
    for (int mi = 0; mi < 4; mi++) {
#pragma unroll
        for (int rr = 0; rr < 2; rr++) {
            const int qrow = qt + wm + mi * 16 + g + rr * 8;
            float* orow = out + ((size_t)b * S_ + qrow) * D_;
#pragma unroll
            for (int ni = 0; ni < 4; ni++) {
                const int col = wn + ni * 8 + c * 2;
                float2 o = { acc[mi][ni][rr * 2 + 0], acc[mi][ni][rr * 2 + 1] };
                *(float2*)&orow[col] = o;
            }
        }
    }
}

// =====================================================================
// d_out = [output (B*S*D) | attn (B*S*S)]
// =====================================================================
extern "C" void kernel_launch(void* const* d_in, const int* in_sizes, int n_in,
                              void* d_out, int out_size)
{
    const float* q    = (const float*)d_in[0];
    const float* k    = (const float*)d_in[1];
    const float* v    = (const float*)d_in[2];
    const float* mask = (const float*)d_in[3];

    float* out  = (float*)d_out;
    float* attn = out + (size_t)B_ * S_ * D_;

    cudaFuncSetAttribute(scores_mma, cudaFuncAttributeMaxDynamicSharedMemorySize, S_SMEM);

    dim3 g1(B_, S_ / 128, S_ / 128);   // b fastest -> L2 reuse of Q/K/mask tiles
    scores_mma<<<g1, 256, S_SMEM>>>(q, k, mask, attn);

    softmax_kernel<<<B_ * S_, 256>>>(attn);

    dim3 g3(B_, S_ / 128);
    out_mma<<<g3, 256>>>(attn, v, out);
}

// round 15
// speedup vs baseline: 1.0186x; 1.0186x over previous
#include <cuda_runtime.h>
#include <cuda_fp16.h>
#include <cstdint>

#define B_ 16
#define S_ 2048
#define D_ 128
#define SCALE_ 0.08838834764831845f  // 1/sqrt(128)

#define QLD_ 136   // halves per Q/K smem row (128 data + 8 pad)
#define CLD_ 132   // floats per staging row (128 data + 4 pad)
#define HLD_ 48    // halves per P smem row (32 data + 16 pad)
#define VLD_ 136   // words per Vs2 pair-row (128 data + 8 pad)
#define SLD_ 36    // floats per P f32 staging row (32 data + 4 pad)

__device__ __forceinline__ uint32_t h2u(half2 h) {
    union { half2 h; uint32_t u; } cvt;
    cvt.h = h;
    return cvt.u;
}

__device__ __forceinline__ uint32_t smem_u32(const void* p) {
    uint32_t a;
    asm("{ .reg .u64 t; cvta.to.shared.u64 t, %1; cvt.u32.u64 %0, t; }" : "=r"(a) : "l"(p));
    return a;
}

// D += A*B, m16n8k16 f16 (f32 accum)
__device__ __forceinline__ void mma16(float* d, uint32_t a0, uint32_t a1, uint32_t a2,
                                      uint32_t a3, uint32_t b0, uint32_t b1) {
    asm volatile(
        "mma.sync.aligned.m16n8k16.row.col.f32.f16.f16.f32 "
        "{%0,%1,%2,%3}, {%4,%5,%6,%7}, {%8,%9}, {%0,%1,%2,%3};"
        : "+f"(d[0]), "+f"(d[1]), "+f"(d[2]), "+f"(d[3])
        : "r"(a0), "r"(a1), "r"(a2), "r"(a3), "r"(b0), "r"(b1));
}

#define LDSM4(r0, r1, r2, r3, a) \
    asm volatile("ldmatrix.sync.aligned.m8n8.x4.shared.b16 {%0,%1,%2,%3}, [%4];" \
                 : "=r"(r0), "=r"(r1), "=r"(r2), "=r"(r3) : "r"(a))

#define CPA16(dst, src) \
    asm volatile("cp.async.cg.shared.global [%0], [%1], 16;" :: "r"(dst), "l"(src))
#define CP_COMMIT() asm volatile("cp.async.commit_group;" ::: "memory")
#define CP_WAIT1()  asm volatile("cp.async.wait_group 1;" ::: "memory")

// Convert float4 -> 4 halves, one STS.64
__device__ __forceinline__ void store_h4(half* rowp, int c4, float4 v) {
    uint2 u = { h2u(__floats2half2_rn(v.x, v.y)), h2u(__floats2half2_rn(v.z, v.w)) };
    *(uint2*)(rowp + c4) = u;
}

// Permuted half store: within each 16-k group, k=2c+h+8e -> pos 4c+2e+h.
__device__ __forceinline__ void store_perm(half* rowp, int c4, float4 v) {
    const int kk0 = c4 & 15;
    const int pos = ((c4 >> 4) << 4) + ((kk0 & 7) << 1) + ((kk0 >> 3) << 1);
    *(half2*)(rowp + pos)     = __floats2half2_rn(v.x, v.y);
    *(half2*)(rowp + pos + 4) = __floats2half2_rn(v.z, v.w);
}

// =====================================================================
// Kernel 1: scores (round-13 exact: full-depth, 1 mainloop barrier,
// smem-staged coalesced epilogue)
// =====================================================================
#define S_SMEM (2 * 128 * QLD_ * 2)   // 69632 B

__global__ __launch_bounds__(256, 2) void scores_mma(
    const float* __restrict__ q, const float* __restrict__ k,
    const float* __restrict__ mask, float* __restrict__ attn)
{
    extern __shared__ half sm[];
    half* Qh = sm;
    half* Kh = sm + 128 * QLD_;
    float* Cs = (float*)sm;

    const int b  = blockIdx.x;
    const int kt = blockIdx.y * 128;
    const int qt = blockIdx.z * 128;

    const float* qb = q + ((size_t)b * S_ + qt) * D_;
    const float* kb = k + ((size_t)b * S_ + kt) * D_;

    const int tid  = threadIdx.x;
    const int wid  = tid >> 5, lane = tid & 31;
    const int g    = lane >> 2, c = lane & 3;
    const int wm   = (wid & 1) * 64;
    const int wn   = (wid >> 1) * 32;

    const uint32_t qbase = smem_u32(Qh);
    const uint32_t kbase = smem_u32(Kh);
    const int l15 = lane & 15;
    const int khi = (lane >> 4) << 3;

    float acc[4][4][4];
#pragma unroll
    for (int mi = 0; mi < 4; mi++)
#pragma unroll
        for (int ni = 0; ni < 4; ni++)
#pragma unroll
            for (int r = 0; r < 4; r++) acc[mi][ni][r] = 0.0f;

#pragma unroll
    for (int t = 0; t < 16; t++) {
        const int idx = tid + t * 256;
        const int row = idx >> 5, c4 = (idx & 31) * 4;
        const float4 vq = *(const float4*)&qb[(size_t)row * D_ + c4];
        store_h4(&Qh[row * QLD_], c4, vq);
    }
#pragma unroll
    for (int t = 0; t < 16; t++) {
        const int idx = tid + t * 256;
        const int row = idx >> 5, c4 = (idx & 31) * 4;
        const float4 vk = *(const float4*)&kb[(size_t)row * D_ + c4];
        store_h4(&Kh[row * QLD_], c4, vk);
    }
    __syncthreads();

#pragma unroll
    for (int kq = 0; kq < 8; kq++) {
        const int koff = kq * 16 + khi;
        uint32_t b0[4], b1[4];
#pragma unroll
        for (int bg = 0; bg < 2; bg++) {
            const uint32_t a = kbase +
                (uint32_t)(((wn + bg * 16 + l15) * QLD_ + koff) << 1);
            LDSM4(b0[2 * bg], b0[2 * bg + 1], b1[2 * bg], b1[2 * bg + 1], a);
        }
#pragma unroll
        for (int mi = 0; mi < 4; mi++) {
            uint32_t a0, a1, a2, a3;
            const uint32_t a = qbase +
                (uint32_t)(((wm + mi * 16 + l15) * QLD_ + koff) << 1);
            LDSM4(a0, a1, a2, a3, a);
#pragma unroll
            for (int ni = 0; ni < 4; ni++)
                mma16(acc[mi][ni], a0, a1, a2, a3, b0[ni], b1[ni]);
        }
    }

    __syncthreads();
#pragma unroll
    for (int mi = 0; mi < 4; mi++) {
#pragma unroll
        for (int rr = 0; rr < 2; rr++) {
            const int row = wm + mi * 16 + g + rr * 8;
#pragma unroll
            for (int ni = 0; ni < 4; ni++) {
                const int col = wn + ni * 8 + c * 2;
                *(float2*)&Cs[row * CLD_ + col] =
                    make_float2(acc[mi][ni][rr * 2 + 0], acc[mi][ni][rr * 2 + 1]);
            }
        }
    }
    __syncthreads();

    const int lane4 = lane * 4;
#pragma unroll
    for (int j = 0; j < 16; j++) {
        const int row = wid * 16 + j;
        const float4 cv = *(const float4*)&Cs[row * CLD_ + lane4];
        const float4 m4 = *(const float4*)&mask[(size_t)(qt + row) * S_ + kt + lane4];
        float4 o;
        o.x = cv.x * SCALE_ + m4.x;
        o.y = cv.y * SCALE_ + m4.y;
        o.z = cv.z * SCALE_ + m4.z;
        o.w = cv.w * SCALE_ + m4.w;
        *(float4*)&attn[((size_t)b * S_ + qt + row) * S_ + kt + lane4] = o;
    }
}

// =====================================================================
// Kernel 2: in-place row softmax (unchanged).
// =====================================================================
__global__ __launch_bounds__(256) void softmax_kernel(float* __restrict__ attn)
{
    __shared__ float red[256];
    const size_t row = blockIdx.x;
    float* p = attn + row * (size_t)S_;
    const int tid = threadIdx.x;

    float4 v0 = ((const float4*)p)[tid];
    float4 v1 = ((const float4*)p)[tid + 256];

    float m = fmaxf(fmaxf(fmaxf(v0.x, v0.y), fmaxf(v0.z, v0.w)),
                    fmaxf(fmaxf(v1.x, v1.y), fmaxf(v1.z, v1.w)));
    red[tid] = m;
    __syncthreads();
#pragma unroll
    for (int s = 128; s > 0; s >>= 1) {
        if (tid < s) red[tid] = fmaxf(red[tid], red[tid + s]);
        __syncthreads();
    }
    m = red[0];
    __syncthreads();

    v0.x = __expf(v0.x - m); v0.y = __expf(v0.y - m);
    v0.z = __expf(v0.z - m); v0.w = __expf(v0.w - m);
    v1.x = __expf(v1.x - m); v1.y = __expf(v1.y - m);
    v1.z = __expf(v1.z - m); v1.w = __expf(v1.w - m);

    float sum = (v0.x + v0.y) + (v0.z + v0.w) + (v1.x + v1.y) + (v1.z + v1.w);
    red[tid] = sum;
    __syncthreads();
#pragma unroll
    for (int s = 128; s > 0; s >>= 1) {
        if (tid < s) red[tid] += red[tid + s];
        __syncthreads();
    }
    const float inv = 1.0f / red[0];

    v0.x *= inv; v0.y *= inv; v0.z *= inv; v0.w *= inv;
    v1.x *= inv; v1.y *= inv; v1.z *= inv; v1.w *= inv;
    ((float4*)p)[tid]       = v0;
    ((float4*)p)[tid + 256] = v1;
}

// =====================================================================
// Kernel 3: out[b,q,d] = sum_s P[b,q,s] * V[b,s,d]
// BK=32, 64 chunks. NEW: cp.async 2-stage double buffer for the P
// stream (raw f32 -> smem staging), convert smem->smem into the
// round-8 permuted Ph. V fill + mma phase verbatim from round 13.
// =====================================================================
#define O_STAGE_W (128 * SLD_)                 // 4608 floats per stage
#define O_SMEM (2 * O_STAGE_W * 4 + 128 * HLD_ * 2 + 16 * VLD_ * 4)  // 57856 B

__global__ __launch_bounds__(256, 2) void out_mma(
    const float* __restrict__ attn, const float* __restrict__ v,
    float* __restrict__ out)
{
    extern __shared__ char osm[];
    float* stage = (float*)osm;                              // [2][128][SLD_]
    half* Ph     = (half*)(osm + 2 * O_STAGE_W * 4);         // [128][HLD_]
    uint32_t* Vs2 = (uint32_t*)(osm + 2 * O_STAGE_W * 4 + 128 * HLD_ * 2);

    const int b  = blockIdx.x;
    const int qt = blockIdx.y * 128;

    const float* pb = attn + ((size_t)b * S_ + qt) * S_;
    const float* vb = v + (size_t)b * S_ * D_;

    const int tid  = threadIdx.x;
    const int wid  = tid >> 5, lane = tid & 31;
    const int g    = lane >> 2, c = lane & 3;
    const int wm   = (wid & 1) * 64;
    const int wn   = (wid >> 1) * 32;

    const int pr    = tid >> 4;         // V pair row 0..15
    const int dbase = (tid & 15) * 4;

    const uint32_t stg = smem_u32(stage);

    // P fill coords: 4 float4 per thread per chunk
    int fr[4], fc[4];
#pragma unroll
    for (int t = 0; t < 4; t++) {
        const int idx = tid + t * 256;
        fr[t] = idx >> 3;
        fc[t] = (idx & 7) * 4;
    }

    float acc[4][4][4];
#pragma unroll
    for (int mi = 0; mi < 4; mi++)
#pragma unroll
        for (int ni = 0; ni < 4; ni++)
#pragma unroll
            for (int r = 0; r < 4; r++) acc[mi][ni][r] = 0.0f;

    // prologue: cp.async chunk 0 into stage 0
#pragma unroll
    for (int t = 0; t < 4; t++)
        CPA16(stg + (uint32_t)(fr[t] * SLD_ + fc[t]) * 4,
              pb + (size_t)fr[t] * S_ + fc[t]);
    CP_COMMIT();

#pragma unroll 1
    for (int s = 0; s < 64; s++) {
        // prefetch chunk s+1 into the other stage
        if (s + 1 < 64) {
            const uint32_t sb = stg + (uint32_t)(((s + 1) & 1) * O_STAGE_W) * 4;
            const int k1 = (s + 1) * 32;
#pragma unroll
            for (int t = 0; t < 4; t++)
                CPA16(sb + (uint32_t)(fr[t] * SLD_ + fc[t]) * 4,
                      pb + (size_t)fr[t] * S_ + k1 + fc[t]);
        }
        CP_COMMIT();
        CP_WAIT1();            // chunk s complete
        __syncthreads();       // stage[s&1] visible; prior mma done -> Ph writable

        // convert P chunk s: smem f32 -> permuted half Ph
        const float* scur = stage + (s & 1) * O_STAGE_W;
#pragma unroll
        for (int t = 0; t < 4; t++) {
            const float4 vp = *(const float4*)&scur[fr[t] * SLD_ + fc[t]];
            store_perm(&Ph[fr[t] * HLD_], fc[t], vp);
        }
        // V fill: pack k-pairs into half2 (L2-resident stream)
        {
            const int k0 = s * 32;
            const float* v0r = vb + (size_t)(k0 + 2 * pr) * D_;
            const float* v1r = v0r + D_;
#pragma unroll
            for (int h = 0; h < 2; h++) {
                const int d = dbase + h * 64;
                const float4 a = *(const float4*)&v0r[d];
                const float4 bb = *(const float4*)&v1r[d];
                uint4 u;
                u.x = h2u(__floats2half2_rn(a.x, bb.x));
                u.y = h2u(__floats2half2_rn(a.y, bb.y));
                u.z = h2u(__floats2half2_rn(a.z, bb.z));
                u.w = h2u(__floats2half2_rn(a.w, bb.w));
                *(uint4*)&Vs2[pr * VLD_ + d] = u;
            }
        }
        __syncthreads();

        // mma phase (round-13 exact)
#pragma unroll
        for (int kq = 0; kq < 2; kq++) {
            const int co = kq * 16 + 4 * c;
            uint32_t bf[4][2];
#pragma unroll
            for (int ni = 0; ni < 4; ni++) {
                const int col = wn + ni * 8 + g;
                bf[ni][0] = Vs2[(kq * 8 + c)     * VLD_ + col];
                bf[ni][1] = Vs2[(kq * 8 + c + 4) * VLD_ + col];
            }
#pragma unroll
            for (int mi = 0; mi < 4; mi++) {
                const int row = wm + mi * 16 + g;
                const uint2 alo = *(const uint2*)&Ph[row * HLD_ + co];
                const uint2 ahi = *(const uint2*)&Ph[(row + 8) * HLD_ + co];
#pragma unroll
                for (int ni = 0; ni < 4; ni++)
                    mma16(acc[mi][ni], alo.x, ahi.x, alo.y, ahi.y, bf[ni][0], bf[ni][1]);
            }
        }
    }

#pragma unroll
    for (int mi = 0; mi < 4; mi++) {
#pragma unroll
        for (int rr = 0; rr < 2; rr++) {
            const int qrow = qt + wm + mi * 16 + g + rr * 8;
            float* orow = out + ((size_t)b * S_ + qrow) * D_;
#pragma unroll
            for (int ni = 0; ni < 4; ni++) {
                const int col = wn + ni * 8 + c * 2;
                float2 o = { acc[mi][ni][rr * 2 + 0], acc[mi][ni][rr * 2 + 1] };
                *(float2*)&orow[col] = o;
            }
        }
    }
}

// =====================================================================
// d_out = [output (B*S*D) | attn (B*S*S)]
// =====================================================================
extern "C" void kernel_launch(void* const* d_in, const int* in_sizes, int n_in,
                              void* d_out, int out_size)
{
    const float* q    = (const float*)d_in[0];
    const float* k    = (const float*)d_in[1];
    const float* v    = (const float*)d_in[2];
    const float* mask = (const float*)d_in[3];

    float* out  = (float*)d_out;
    float* attn = out + (size_t)B_ * S_ * D_;

    cudaFuncSetAttribute(scores_mma, cudaFuncAttributeMaxDynamicSharedMemorySize, S_SMEM);
    cudaFuncSetAttribute(out_mma,    cudaFuncAttributeMaxDynamicSharedMemorySize, O_SMEM);

    dim3 g1(B_, S_ / 128, S_ / 128);   // b fastest -> L2 reuse of Q/K/mask tiles
    scores_mma<<<g1, 256, S_SMEM>>>(q, k, mask, attn);

    softmax_kernel<<<B_ * S_, 256>>>(attn);

    dim3 g3(B_, S_ / 128);
    out_mma<<<g3, 256, O_SMEM>>>(attn, v, out);
}

// round 16
// speedup vs baseline: 1.1006x; 1.0805x over previous
#include <cuda_runtime.h>
#include <cuda_fp16.h>
#include <cstdint>

#define B_ 16
#define S_ 2048
#define D_ 128
#define SCALE_ 0.08838834764831845f  // 1/sqrt(128)

#define QLD_ 136   // halves per Q/K smem row (128 data + 8 pad)
#define CLD_ 132   // floats per staging row (128 data + 4 pad)
#define HLD_ 48    // halves per P smem row (32 data + 16 pad)
#define VLD_ 136   // words per Vs2 pair-row (128 data + 8 pad)

// Pre-packed operands for out_mma
__device__ half     g_phalf[(size_t)B_ * S_ * S_];        // 128 MB, perm-packed P
__device__ uint32_t g_vpair[(size_t)B_ * (S_ / 2) * D_];  // 8 MB, half2 k-paired V

__device__ __forceinline__ uint32_t h2u(half2 h) {
    union { half2 h; uint32_t u; } cvt;
    cvt.h = h;
    return cvt.u;
}

__device__ __forceinline__ uint32_t smem_u32(const void* p) {
    uint32_t a;
    asm("{ .reg .u64 t; cvta.to.shared.u64 t, %1; cvt.u32.u64 %0, t; }" : "=r"(a) : "l"(p));
    return a;
}

// D += A*B, m16n8k16 f16 (f32 accum)
__device__ __forceinline__ void mma16(float* d, uint32_t a0, uint32_t a1, uint32_t a2,
                                      uint32_t a3, uint32_t b0, uint32_t b1) {
    asm volatile(
        "mma.sync.aligned.m16n8k16.row.col.f32.f16.f16.f32 "
        "{%0,%1,%2,%3}, {%4,%5,%6,%7}, {%8,%9}, {%0,%1,%2,%3};"
        : "+f"(d[0]), "+f"(d[1]), "+f"(d[2]), "+f"(d[3])
        : "r"(a0), "r"(a1), "r"(a2), "r"(a3), "r"(b0), "r"(b1));
}

#define LDSM4(r0, r1, r2, r3, a) \
    asm volatile("ldmatrix.sync.aligned.m8n8.x4.shared.b16 {%0,%1,%2,%3}, [%4];" \
                 : "=r"(r0), "=r"(r1), "=r"(r2), "=r"(r3) : "r"(a))

#define CPA16(dst, src) \
    asm volatile("cp.async.cg.shared.global [%0], [%1], 16;" :: "r"(dst), "l"(src))
#define CP_COMMIT() asm volatile("cp.async.commit_group;" ::: "memory")
#define CP_WAIT1()  asm volatile("cp.async.wait_group 1;" ::: "memory")

// Convert float4 -> 4 halves, one STS.64
__device__ __forceinline__ void store_h4(half* rowp, int c4, float4 v) {
    uint2 u = { h2u(__floats2half2_rn(v.x, v.y)), h2u(__floats2half2_rn(v.z, v.w)) };
    *(uint2*)(rowp + c4) = u;
}

// Permuted half store: within each 16-k group, k=2c+h+8e -> pos 4c+2e+h.
// Works for any c4 multiple of 4 (group base preserved by (c4>>4)<<4).
__device__ __forceinline__ void store_perm(half* rowp, int c4, float4 v) {
    const int kk0 = c4 & 15;
    const int pos = ((c4 >> 4) << 4) + ((kk0 & 7) << 1) + ((kk0 >> 3) << 1);
    *(half2*)(rowp + pos)     = __floats2half2_rn(v.x, v.y);
    *(half2*)(rowp + pos + 4) = __floats2half2_rn(v.z, v.w);
}

// =====================================================================
// Kernel 0: pre-pack V -> half2 k-pairs. g_vpair[b][p][d] =
// half2(V[b][2p][d], V[b][2p+1][d]). 2048 blocks x 256 threads.
// =====================================================================
__global__ __launch_bounds__(256) void vprep_kernel(const float* __restrict__ v)
{
    const int idx = blockIdx.x * 256 + threadIdx.x;   // uint4 index
    const int d4 = (idx & 31) * 4;
    const int p  = (idx >> 5) & 1023;
    const int b  = idx >> 15;
    const float* r0 = v + ((size_t)b * S_ + 2 * p) * D_ + d4;
    const float* r1 = r0 + D_;
    const float4 a = *(const float4*)r0;
    const float4 c = *(const float4*)r1;
    uint4 u;
    u.x = h2u(__floats2half2_rn(a.x, c.x));
    u.y = h2u(__floats2half2_rn(a.y, c.y));
    u.z = h2u(__floats2half2_rn(a.z, c.z));
    u.w = h2u(__floats2half2_rn(a.w, c.w));
    *(uint4*)&g_vpair[((size_t)b * (S_ / 2) + p) * D_ + d4] = u;
}

// =====================================================================
// Kernel 1: scores (round-13 exact)
// =====================================================================
#define S_SMEM (2 * 128 * QLD_ * 2)   // 69632 B

__global__ __launch_bounds__(256, 2) void scores_mma(
    const float* __restrict__ q, const float* __restrict__ k,
    const float* __restrict__ mask, float* __restrict__ attn)
{
    extern __shared__ half sm[];
    half* Qh = sm;
    half* Kh = sm + 128 * QLD_;
    float* Cs = (float*)sm;

    const int b  = blockIdx.x;
    const int kt = blockIdx.y * 128;
    const int qt = blockIdx.z * 128;

    const float* qb = q + ((size_t)b * S_ + qt) * D_;
    const float* kb = k + ((size_t)b * S_ + kt) * D_;

    const int tid  = threadIdx.x;
    const int wid  = tid >> 5, lane = tid & 31;
    const int g    = lane >> 2, c = lane & 3;
    const int wm   = (wid & 1) * 64;
    const int wn   = (wid >> 1) * 32;

    const uint32_t qbase = smem_u32(Qh);
    const uint32_t kbase = smem_u32(Kh);
    const int l15 = lane & 15;
    const int khi = (lane >> 4) << 3;

    float acc[4][4][4];
#pragma unroll
    for (int mi = 0; mi < 4; mi++)
#pragma unroll
        for (int ni = 0; ni < 4; ni++)
#pragma unroll
            for (int r = 0; r < 4; r++) acc[mi][ni][r] = 0.0f;

#pragma unroll
    for (int t = 0; t < 16; t++) {
        const int idx = tid + t * 256;
        const int row = idx >> 5, c4 = (idx & 31) * 4;
        const float4 vq = *(const float4*)&qb[(size_t)row * D_ + c4];
        store_h4(&Qh[row * QLD_], c4, vq);
    }
#pragma unroll
    for (int t = 0; t < 16; t++) {
        const int idx = tid + t * 256;
        const int row = idx >> 5, c4 = (idx & 31) * 4;
        const float4 vk = *(const float4*)&kb[(size_t)row * D_ + c4];
        store_h4(&Kh[row * QLD_], c4, vk);
    }
    __syncthreads();

#pragma unroll
    for (int kq = 0; kq < 8; kq++) {
        const int koff = kq * 16 + khi;
        uint32_t b0[4], b1[4];
#pragma unroll
        for (int bg = 0; bg < 2; bg++) {
            const uint32_t a = kbase +
                (uint32_t)(((wn + bg * 16 + l15) * QLD_ + koff) << 1);
            LDSM4(b0[2 * bg], b0[2 * bg + 1], b1[2 * bg], b1[2 * bg + 1], a);
        }
#pragma unroll
        for (int mi = 0; mi < 4; mi++) {
            uint32_t a0, a1, a2, a3;
            const uint32_t a = qbase +
                (uint32_t)(((wm + mi * 16 + l15) * QLD_ + koff) << 1);
            LDSM4(a0, a1, a2, a3, a);
#pragma unroll
            for (int ni = 0; ni < 4; ni++)
                mma16(acc[mi][ni], a0, a1, a2, a3, b0[ni], b1[ni]);
        }
    }

    __syncthreads();
#pragma unroll
    for (int mi = 0; mi < 4; mi++) {
#pragma unroll
        for (int rr = 0; rr < 2; rr++) {
            const int row = wm + mi * 16 + g + rr * 8;
#pragma unroll
            for (int ni = 0; ni < 4; ni++) {
                const int col = wn + ni * 8 + c * 2;
                *(float2*)&Cs[row * CLD_ + col] =
                    make_float2(acc[mi][ni][rr * 2 + 0], acc[mi][ni][rr * 2 + 1]);
            }
        }
    }
    __syncthreads();

    const int lane4 = lane * 4;
#pragma unroll
    for (int j = 0; j < 16; j++) {
        const int row = wid * 16 + j;
        const float4 cv = *(const float4*)&Cs[row * CLD_ + lane4];
        const float4 m4 = *(const float4*)&mask[(size_t)(qt + row) * S_ + kt + lane4];
        float4 o;
        o.x = cv.x * SCALE_ + m4.x;
        o.y = cv.y * SCALE_ + m4.y;
        o.z = cv.z * SCALE_ + m4.z;
        o.w = cv.w * SCALE_ + m4.w;
        *(float4*)&attn[((size_t)b * S_ + qt + row) * S_ + kt + lane4] = o;
    }
}

// =====================================================================
// Kernel 2: row softmax. Writes fp32 attn in place AND perm-packed
// half copy to g_phalf. Warp-shuffle reductions (2 barriers).
// =====================================================================
__global__ __launch_bounds__(256) void softmax_kernel(float* __restrict__ attn)
{
    __shared__ float redm[8], reds[8];
    const size_t row = blockIdx.x;
    float* p = attn + row * (size_t)S_;
    half* ph = g_phalf + row * (size_t)S_;
    const int tid = threadIdx.x;
    const int wid = tid >> 5, lane = tid & 31;

    float4 v0 = ((const float4*)p)[tid];
    float4 v1 = ((const float4*)p)[tid + 256];

    float m = fmaxf(fmaxf(fmaxf(v0.x, v0.y), fmaxf(v0.z, v0.w)),
                    fmaxf(fmaxf(v1.x, v1.y), fmaxf(v1.z, v1.w)));
#pragma unroll
    for (int o = 16; o > 0; o >>= 1)
        m = fmaxf(m, __shfl_xor_sync(0xFFFFFFFF, m, o));
    if (lane == 0) redm[wid] = m;
    __syncthreads();
    m = fmaxf(fmaxf(fmaxf(redm[0], redm[1]), fmaxf(redm[2], redm[3])),
              fmaxf(fmaxf(redm[4], redm[5]), fmaxf(redm[6], redm[7])));

    v0.x = __expf(v0.x - m); v0.y = __expf(v0.y - m);
    v0.z = __expf(v0.z - m); v0.w = __expf(v0.w - m);
    v1.x = __expf(v1.x - m); v1.y = __expf(v1.y - m);
    v1.z = __expf(v1.z - m); v1.w = __expf(v1.w - m);

    float s = (v0.x + v0.y) + (v0.z + v0.w) + (v1.x + v1.y) + (v1.z + v1.w);
#pragma unroll
    for (int o = 16; o > 0; o >>= 1)
        s += __shfl_xor_sync(0xFFFFFFFF, s, o);
    if (lane == 0) reds[wid] = s;
    __syncthreads();
    const float inv = 1.0f / (((reds[0] + reds[1]) + (reds[2] + reds[3])) +
                              ((reds[4] + reds[5]) + (reds[6] + reds[7])));

    v0.x *= inv; v0.y *= inv; v0.z *= inv; v0.w *= inv;
    v1.x *= inv; v1.y *= inv; v1.z *= inv; v1.w *= inv;
    ((float4*)p)[tid]       = v0;
    ((float4*)p)[tid + 256] = v1;

    // perm-packed half copy for out_mma's A operand
    store_perm(ph, tid * 4, v0);
    store_perm(ph, (tid + 256) * 4, v1);
}

// =====================================================================
// Kernel 3: out[b,q,d] = sum_s P[b,q,s] * V[b,s,d]
// Fill phase = pure cp.async of pre-packed operands (double buffered).
// mma phase identical to round 13/15.
// =====================================================================
__global__ __launch_bounds__(256, 2) void out_mma(float* __restrict__ out)
{
    __shared__ half Ph2[2][128 * HLD_];        // 24 KB
    __shared__ uint32_t Vs2[2][16 * VLD_];     // 17.4 KB

    const int b  = blockIdx.x;
    const int qt = blockIdx.y * 128;

    const half* pb = g_phalf + ((size_t)b * S_ + qt) * S_;
    const uint32_t* vb = g_vpair + (size_t)b * (S_ / 2) * D_;

    const int tid  = threadIdx.x;
    const int wid  = tid >> 5, lane = tid & 31;
    const int g    = lane >> 2, c = lane & 3;
    const int wm   = (wid & 1) * 64;
    const int wn   = (wid >> 1) * 32;

    const uint32_t phb = smem_u32(Ph2);
    const uint32_t vsb = smem_u32(Vs2);

    // P copy coords: 512 x 16B per chunk -> 2 per thread
    // row = idx>>2 (4 x 16B per row's 64B), c16 = idx&3
    // V copy coords: 512 x 16B per chunk -> 2 per thread
    // row = idx>>5 (32 x 16B per row's 512B), c16 = idx&31
    float acc[4][4][4];
#pragma unroll
    for (int mi = 0; mi < 4; mi++)
#pragma unroll
        for (int ni = 0; ni < 4; ni++)
#pragma unroll
            for (int r = 0; r < 4; r++) acc[mi][ni][r] = 0.0f;

    // prologue: issue chunks 0 and 1
#pragma unroll
    for (int ch = 0; ch < 2; ch++) {
        const int k0 = ch * 32;
        const uint32_t pdst = phb + (uint32_t)ch * (128 * HLD_ * 2);
        const uint32_t vdst = vsb + (uint32_t)ch * (16 * VLD_ * 4);
#pragma unroll
        for (int t = 0; t < 2; t++) {
            const int idx = tid + t * 256;
            const int prow = idx >> 2, pc16 = idx & 3;
            CPA16(pdst + (uint32_t)(prow * HLD_ * 2 + pc16 * 16),
                  pb + (size_t)prow * S_ + k0 + pc16 * 8);
            const int vrow = idx >> 5, vc16 = idx & 31;
            CPA16(vdst + (uint32_t)(vrow * VLD_ * 4 + vc16 * 16),
                  vb + (size_t)(k0 / 2 + vrow) * D_ + vc16 * 4);
        }
        CP_COMMIT();
    }

#pragma unroll 1
    for (int s = 0; s < 64; s++) {
        CP_WAIT1();            // chunk s complete
        __syncthreads();

        const half* Ph = Ph2[s & 1];
        const uint32_t* Vs = Vs2[s & 1];
#pragma unroll
        for (int kq = 0; kq < 2; kq++) {
            const int co = kq * 16 + 4 * c;
            uint32_t bf[4][2];
#pragma unroll
            for (int ni = 0; ni < 4; ni++) {
                const int col = wn + ni * 8 + g;
                bf[ni][0] = Vs[(kq * 8 + c)     * VLD_ + col];
                bf[ni][1] = Vs[(kq * 8 + c + 4) * VLD_ + col];
            }
#pragma unroll
            for (int mi = 0; mi < 4; mi++) {
                const int row = wm + mi * 16 + g;
                const uint2 alo = *(const uint2*)&Ph[row * HLD_ + co];
                const uint2 ahi = *(const uint2*)&Ph[(row + 8) * HLD_ + co];
#pragma unroll
                for (int ni = 0; ni < 4; ni++)
                    mma16(acc[mi][ni], alo.x, ahi.x, alo.y, ahi.y, bf[ni][0], bf[ni][1]);
            }
        }
        __syncthreads();       // all reads of buf (s&1) done

        if (s + 2 < 64) {
            const int k0 = (s + 2) * 32;
            const uint32_t pdst = phb + (uint32_t)(s & 1) * (128 * HLD_ * 2);
            const uint32_t vdst = vsb + (uint32_t)(s & 1) * (16 * VLD_ * 4);
#pragma unroll
            for (int t = 0; t < 2; t++) {
                const int idx = tid + t * 256;
                const int prow = idx >> 2, pc16 = idx & 3;
                CPA16(pdst + (uint32_t)(prow * HLD_ * 2 + pc16 * 16),
                      pb + (size_t)prow * S_ + k0 + pc16 * 8);
                const int vrow = idx >> 5, vc16 = idx & 31;
                CPA16(vdst + (uint32_t)(vrow * VLD_ * 4 + vc16 * 16),
                      vb + (size_t)(k0 / 2 + vrow) * D_ + vc16 * 4);
            }
        }
        CP_COMMIT();
    }

#pragma unroll
    for (int mi = 0; mi < 4; mi++) {
#pragma unroll
        for (int rr = 0; rr < 2; rr++) {
            const int qrow = qt + wm + mi * 16 + g + rr * 8;
            float* orow = out + ((size_t)b * S_ + qrow) * D_;
#pragma unroll
            for (int ni = 0; ni < 4; ni++) {
                const int col = wn + ni * 8 + c * 2;
                float2 o = { acc[mi][ni][rr * 2 + 0], acc[mi][ni][rr * 2 + 1] };
                *(float2*)&orow[col] = o;
            }
        }
    }
}

// =====================================================================
// d_out = [output (B*S*D) | attn (B*S*S)]
// =====================================================================
extern "C" void kernel_launch(void* const* d_in, const int* in_sizes, int n_in,
                              void* d_out, int out_size)
{
    const float* q    = (const float*)d_in[0];
    const float* k    = (const float*)d_in[1];
    const float* v    = (const float*)d_in[2];
    const float* mask = (const float*)d_in[3];

    float* out  = (float*)d_out;
    float* attn = out + (size_t)B_ * S_ * D_;

    cudaFuncSetAttribute(scores_mma, cudaFuncAttributeMaxDynamicSharedMemorySize, S_SMEM);

    vprep_kernel<<<2048, 256>>>(v);

    dim3 g1(B_, S_ / 128, S_ / 128);   // b fastest -> L2 reuse of Q/K/mask tiles
    scores_mma<<<g1, 256, S_SMEM>>>(q, k, mask, attn);

    softmax_kernel<<<B_ * S_, 256>>>(attn);

    dim3 g3(B_, S_ / 128);
    out_mma<<<g3, 256>>>(out);
}